// round 6
// baseline (speedup 1.0000x reference)
#include <cuda_runtime.h>
#include <cstddef>

// Problem constants
#define TA      262144      // T*A = 2048*128
#define D_OBS   64
#define NTP     4
#define DIN     68          // D_OBS + NTP
#define HDIM    64
#define NA      16
#define OUTC    17          // NA + 1 (value)
#define TILE    128         // rows per tile
#define NTHR    512
#define NCTA    296         // persistent CTAs (2 per SM on 148 SMs)
#define ECTAS   37          // CTAs per expert (4*37 = 148)
#define LDX     68          // row stride for X/H tiles (8 consecutive rows -> 32 banks)

// ---------------- scratch ----------------
__device__ int g_perm[NTP * TA];   // per-expert buckets at base e*TA
__device__ int g_cnt[NTP];
__device__ int g_flag;             // 1 => hete_pick stored as int32, 0 => int64

// ---------------- f32x2 helpers ----------------
#define FMA2(acc, a, b) \
    asm("fma.rn.f32x2 %0, %1, %2, %0;" : "+l"(acc) : "l"(a), "l"(b))
#define PACK_DUP(d, x) \
    asm("mov.b64 %0, {%1, %1};" : "=l"(d) : "r"(__float_as_uint(x)))
#define ADD2(d, a, b) \
    asm("add.rn.f32x2 %0, %1, %2;" : "=l"(d) : "l"(a), "l"(b))
#define UNPACK2(lo, hi, v) \
    asm("mov.b64 {%0, %1}, %2;" : "=r"(lo), "=r"(hi) : "l"(v))

typedef unsigned long long u64;

// ---------------- prologue kernels ----------------
__global__ void k_init() {
    int t = threadIdx.x;
    if (t < NTP) g_cnt[t] = 0;
    if (t == NTP) g_flag = 0;
}

// Detect int32 vs int64 storage of hete_pick (int64 LE: odd words all zero).
__global__ void k_detect(const int* __restrict__ h) {
    int stride = gridDim.x * blockDim.x;
    int acc = 0;
    for (int j = blockIdx.x * blockDim.x + threadIdx.x; j < TA / 2; j += stride)
        acc |= h[2 * j + 1];
    unsigned any = __ballot_sync(0xffffffffu, acc != 0);
    if ((threadIdx.x & 31) == 0 && any) atomicOr(&g_flag, 1);
}

__device__ __forceinline__ int pick_at(const int* __restrict__ h, int i, int f) {
    return f ? h[i] : h[2 * i];
}

// Block-aggregated classify+scatter into per-expert buckets.
__global__ void k_build(const int* __restrict__ h) {
    __shared__ int sHist[NTP], sBase[NTP], sRank[NTP];
    int tid = threadIdx.x;
    if (tid < NTP) { sHist[tid] = 0; sRank[tid] = 0; }
    __syncthreads();
    int f = g_flag;
    int i = blockIdx.x * 512 + tid;
    int t = pick_at(h, i, f);
    atomicAdd(&sHist[t], 1);
    __syncthreads();
    if (tid < NTP) sBase[tid] = atomicAdd(&g_cnt[tid], sHist[tid]);
    __syncthreads();
    int p = atomicAdd(&sRank[t], 1);
    g_perm[t * TA + sBase[t] + p] = i;
}

// ---------------- shared layout (floats) ----------------
#define OFF_W1   0                          // [68][64] k-major
#define OFF_W2   (OFF_W1 + DIN * HDIM)      // 4352  [64][64]
#define OFF_W3   (OFF_W2 + HDIM * HDIM)     // 8448  [64][16]
#define OFF_VW   (OFF_W3 + HDIM * NA)       // 9472  critic W3 vector [64]
#define OFF_B1   (OFF_VW + 64)              // 9536
#define OFF_B2   (OFF_B1 + 64)              // 9600
#define OFF_B3   (OFF_B2 + 64)              // 9664
#define OFF_VB   (OFF_B3 + 16)              // 9680
#define OFF_X    (OFF_VB + 4)               // 9684  [128][68]
#define OFF_H1   (OFF_X + TILE * LDX)       // 18388 [128][68]
#define OFF_ROWS (OFF_H1 + TILE * LDX)      // 27092 (ints)
#define SMEM_FLOATS (OFF_ROWS + TILE)       // 27220
#define SMEM_BYTES  (SMEM_FLOATS * 4)       // 108880

extern __shared__ float smem[];

// out[128][64] = act(in[128][KD] @ W + b). W native k-major smem: sW[k][c].
// 16 warps = 4 row-groups x 4 col-groups (32 rows x 16 cols each).
// Thread = rows {rg*32+8j+(lane&7)} x cols {cg*16+(lane>>3)*4 .. +3}.
// X LDS.128: 8 consecutive rows -> 1 wavefront; W LDS.128: 4 distinct 16B -> 1 wf.
template <int KD, bool RELU>
__device__ __forceinline__ void layer64(const float* __restrict__ sIn,
                                        const float* __restrict__ sW,
                                        const float* __restrict__ sB,
                                        float* __restrict__ sOut, int tid) {
    const int lane = tid & 31;
    const int warp = tid >> 5;
    const int rbase = (warp >> 2) * 32 + (lane & 7);   // + 8j
    const int c0 = (warp & 3) * 16 + (lane >> 3) * 4;

    u64 acc[4][2];
#pragma unroll
    for (int j = 0; j < 4; j++) { acc[j][0] = 0ull; acc[j][1] = 0ull; }

    for (int k = 0; k < KD; k += 4) {
        float4 xv[4];
#pragma unroll
        for (int j = 0; j < 4; j++)
            xv[j] = *(const float4*)&sIn[(rbase + 8 * j) * LDX + k];
#pragma unroll
        for (int kk = 0; kk < 4; kk++) {
            ulonglong2 w = *(const ulonglong2*)&sW[(k + kk) * HDIM + c0];
#pragma unroll
            for (int j = 0; j < 4; j++) {
                float xs = (kk == 0) ? xv[j].x : (kk == 1) ? xv[j].y
                         : (kk == 2) ? xv[j].z : xv[j].w;
                u64 bx;
                PACK_DUP(bx, xs);
                FMA2(acc[j][0], bx, w.x);
                FMA2(acc[j][1], bx, w.y);
            }
        }
    }

    float4 b = *(const float4*)&sB[c0];
#pragma unroll
    for (int j = 0; j < 4; j++) {
        int row = rbase + 8 * j;
        unsigned u0, u1, u2, u3;
        UNPACK2(u0, u1, acc[j][0]);
        UNPACK2(u2, u3, acc[j][1]);
        float4 o;
        o.x = __uint_as_float(u0) + b.x;
        o.y = __uint_as_float(u1) + b.y;
        o.z = __uint_as_float(u2) + b.z;
        o.w = __uint_as_float(u3) + b.w;
        if (RELU) {
            o.x = fmaxf(o.x, 0.0f); o.y = fmaxf(o.y, 0.0f);
            o.z = fmaxf(o.z, 0.0f); o.w = fmaxf(o.w, 0.0f);
        }
        *(float4*)&sOut[row * LDX + c0] = o;
    }
}

__global__ void __launch_bounds__(NTHR, 2) mlp_kernel(
    const float* __restrict__ obs, const float* __restrict__ gp,
    const float* __restrict__ W1, const float* __restrict__ b1,
    const float* __restrict__ W2, const float* __restrict__ b2,
    const float* __restrict__ W3, const float* __restrict__ b3,
    const float* __restrict__ cW1, const float* __restrict__ cb1,
    const float* __restrict__ cW2, const float* __restrict__ cb2,
    const float* __restrict__ cW3, const float* __restrict__ cb3,
    float* __restrict__ out) {
    float* sW1 = smem + OFF_W1;
    float* sW2 = smem + OFF_W2;
    float* sW3 = smem + OFF_W3;
    float* sVW = smem + OFF_VW;
    float* sB1 = smem + OFF_B1;
    float* sB2 = smem + OFF_B2;
    float* sB3 = smem + OFF_B3;
    float* sVB = smem + OFF_VB;
    float* sX  = smem + OFF_X;
    float* sH1 = smem + OFF_H1;
    float* sH2 = sX;  // reuse X buffer after layer 1 (stride LDX)
    int*   sRows = (int*)(smem + OFF_ROWS);

    const int tid = threadIdx.x;
    const int c = blockIdx.x;
    const bool critic = (c >= 4 * ECTAS);

    int e = 0, j0, tstride, ntiles;
    if (!critic) {
        e = c / ECTAS;
        j0 = c - e * ECTAS;
        tstride = ECTAS;
        ntiles = (g_cnt[e] + TILE - 1) / TILE;
    } else {
        j0 = c - 4 * ECTAS;
        tstride = NCTA - 4 * ECTAS;   // 148
        ntiles = TA / TILE;           // 2048
    }

    // ---- stage weights ONCE (native layout: straight copy) ----
    {
        const float* w1p = critic ? cW1 : (W1 + (size_t)e * DIN * HDIM);
        const float* w2p = critic ? cW2 : (W2 + (size_t)e * HDIM * HDIM);
        for (int i = tid; i < DIN * HDIM / 4; i += NTHR)
            ((float4*)sW1)[i] = ((const float4*)w1p)[i];
        for (int i = tid; i < HDIM * HDIM / 4; i += NTHR)
            ((float4*)sW2)[i] = ((const float4*)w2p)[i];
        if (!critic) {
            const float* w3p = W3 + (size_t)e * HDIM * NA;
            for (int i = tid; i < HDIM * NA / 4; i += NTHR)
                ((float4*)sW3)[i] = ((const float4*)w3p)[i];
            if (tid < HDIM) { sB1[tid] = b1[e * HDIM + tid]; sB2[tid] = b2[e * HDIM + tid]; }
            if (tid < NA) sB3[tid] = b3[e * NA + tid];
        } else {
            if (tid < HDIM) { sVW[tid] = cW3[tid]; sB1[tid] = cb1[tid]; sB2[tid] = cb2[tid]; }
            if (tid == 0) sVB[0] = cb3[0];
        }
    }

    const int cnt = critic ? TA : g_cnt[e];
    const int* permBase = g_perm + e * TA;

    // ---- persistent tile loop ----
    for (int t = j0; t < ntiles; t += tstride) {
        const int start = t * TILE;
        const int nvalid = min(TILE, cnt - start);

        __syncthreads();   // protect sX/sH2/sRows reuse (covers staging on iter 0)

        // stage X tile inline: each thread handles 4 (r,q) slots; row index
        // fetched directly from perm (L1-broadcast across the 16 threads of a row).
        for (int idx = tid; idx < TILE * 16; idx += NTHR) {
            int r = idx >> 4, q = idx & 15;
            int row;
            if (critic) row = start + r;
            else row = (r < nvalid) ? permBase[start + r] : 0;
            float4 v = *(const float4*)(obs + (size_t)row * D_OBS + q * 4);
            *(float4*)&sX[r * LDX + q * 4] = v;
            if (q == 0) {
                sRows[r] = row;
                int tenv = row >> 7;   // row / 128 agents
                *(float4*)&sX[r * LDX + D_OBS] = *(const float4*)(gp + tenv * NTP);
            }
        }
        __syncthreads();

        layer64<DIN, true>(sX, sW1, sB1, sH1, tid);
        __syncthreads();
        layer64<HDIM, true>(sH1, sW2, sB2, sH2, tid);
        __syncthreads();

        if (!critic) {
            // logits 128x16: warp = 32 rows x 4 cols; thread = 4 rows x 1 pair
            // x half-of-k; cross-half combine via 64-bit shfl.
            const int lane = tid & 31;
            const int warp = tid >> 5;
            const int rbase = (warp >> 2) * 32 + (lane & 7);
            const int cp = (warp & 3) * 4 + ((lane >> 3) & 1) * 2;
            const int kh = (lane >> 4) * 32;  // k half: 0 or 32
            u64 acc[4];
#pragma unroll
            for (int j = 0; j < 4; j++) acc[j] = 0ull;
            for (int k0 = 0; k0 < 32; k0 += 4) {
                int k = kh + k0;
                float4 xv[4];
#pragma unroll
                for (int j = 0; j < 4; j++)
                    xv[j] = *(const float4*)&sH2[(rbase + 8 * j) * LDX + k];
#pragma unroll
                for (int kk = 0; kk < 4; kk++) {
                    u64 w = *(const u64*)&sW3[(k + kk) * NA + cp];
#pragma unroll
                    for (int j = 0; j < 4; j++) {
                        float xs = (kk == 0) ? xv[j].x : (kk == 1) ? xv[j].y
                                 : (kk == 2) ? xv[j].z : xv[j].w;
                        u64 bx;
                        PACK_DUP(bx, xs);
                        FMA2(acc[j], bx, w);
                    }
                }
            }
            float bc0 = sB3[cp], bc1 = sB3[cp + 1];
#pragma unroll
            for (int j = 0; j < 4; j++) {
                u64 other = __shfl_xor_sync(0xffffffffu, acc[j], 16);
                u64 s;
                ADD2(s, acc[j], other);
                int r = rbase + 8 * j;
                unsigned lo, hi;
                UNPACK2(lo, hi, s);
                if ((lane >> 4) == 0 && r < nvalid) {
                    size_t o = (size_t)sRows[r] * OUTC + cp;
                    out[o] = __uint_as_float(lo) + bc0;
                    out[o + 1] = __uint_as_float(hi) + bc1;
                }
            }
        } else {
            // value column: 4 threads per row (16 k each), k-parity f32x2
            const int r = tid >> 2;
            const int p = tid & 3;
            u64 acc = 0ull;
            for (int kk = 0; kk < 16; kk += 4) {
                int k = p * 16 + kk;
                ulonglong2 h = *(const ulonglong2*)&sH2[r * LDX + k];
                ulonglong2 w = *(const ulonglong2*)&sVW[k];
                FMA2(acc, h.x, w.x);
                FMA2(acc, h.y, w.y);
            }
            unsigned lo, hi;
            UNPACK2(lo, hi, acc);
            float a = __uint_as_float(lo) + __uint_as_float(hi);
            a += __shfl_xor_sync(0xffffffffu, a, 1);
            a += __shfl_xor_sync(0xffffffffu, a, 2);
            if (p == 0)
                out[(size_t)(start + r) * OUTC + NA] = a + sVB[0];
        }
    }
}

// ---------------- launch ----------------
extern "C" void kernel_launch(void* const* d_in, const int* in_sizes, int n_in,
                              void* d_out, int out_size) {
    const float* obs  = (const float*)d_in[0];
    const int*   hete = (const int*)d_in[1];
    const float* gp   = (const float*)d_in[2];
    const float* W1   = (const float*)d_in[3];
    const float* b1   = (const float*)d_in[4];
    const float* W2   = (const float*)d_in[5];
    const float* b2   = (const float*)d_in[6];
    const float* W3   = (const float*)d_in[7];
    const float* b3   = (const float*)d_in[8];
    const float* cW1  = (const float*)d_in[9];
    const float* cb1  = (const float*)d_in[10];
    const float* cW2  = (const float*)d_in[11];
    const float* cb2  = (const float*)d_in[12];
    const float* cW3  = (const float*)d_in[13];
    const float* cb3  = (const float*)d_in[14];
    float* out = (float*)d_out;

    cudaFuncSetAttribute(mlp_kernel, cudaFuncAttributeMaxDynamicSharedMemorySize,
                         SMEM_BYTES);

    k_init<<<1, 32>>>();
    k_detect<<<128, 256>>>(hete);
    k_build<<<TA / 512, 512>>>(hete);

    mlp_kernel<<<NCTA, NTHR, SMEM_BYTES>>>(obs, gp, W1, b1, W2, b2, W3, b3,
                                           cW1, cb1, cW2, cb2, cW3, cb3, out);
}

// round 8
// speedup vs baseline: 1.8962x; 1.8962x over previous
#include <cuda_runtime.h>
#include <cuda_bf16.h>
#include <cstdint>
#include <cstddef>

#define TA      262144      // T*A = 2048*128
#define D_OBS   64
#define NTP     4
#define HDIM    64
#define NA      16
#define OUTC    17
#define TILE    128
#define NTHR    256
#define NCTA    296         // persistent, 2/SM
#define ECTAS   37          // per expert (4*37=148), critic gets 148

// u32-strides for pair-packed smem arrays (bank-conflict-free, see analysis)
#define APS     44          // AP[row][kp], kp 0..39 (K=80 padded)
#define W12S    72          // WP[kp][n],  n 0..63
#define W3S     40          // WP3[kp][n], n 0..15

typedef unsigned long long u64;

// ---------------- scratch ----------------
__device__ int g_perm[NTP * TA];
__device__ int g_cnt[NTP];
__device__ int g_flag;

// ---------------- helpers ----------------
__device__ __forceinline__ uint32_t cvt_bf2(float lo, float hi) {
    uint32_t r;
    asm("cvt.rn.bf16x2.f32 %0, %1, %2;" : "=r"(r) : "f"(hi), "f"(lo));
    return r;   // low 16 bits = bf16(lo), high = bf16(hi)
}
__device__ __forceinline__ void split2(float v0, float v1, uint32_t& uh, uint32_t& ul) {
    uh = cvt_bf2(v0, v1);
    float r0 = v0 - __uint_as_float(uh << 16);
    float r1 = v1 - __uint_as_float(uh & 0xffff0000u);
    ul = cvt_bf2(r0, r1);
}

// m16n8k16 row.col bf16 -> f32
#define MMA_BF16(c, a, b0, b1) \
    asm volatile("mma.sync.aligned.m16n8k16.row.col.f32.bf16.bf16.f32 " \
        "{%0,%1,%2,%3},{%4,%5,%6,%7},{%8,%9},{%0,%1,%2,%3};" \
        : "+f"((c)[0]), "+f"((c)[1]), "+f"((c)[2]), "+f"((c)[3]) \
        : "r"((a)[0]), "r"((a)[1]), "r"((a)[2]), "r"((a)[3]), "r"(b0), "r"(b1))

// ---------------- prologue kernels ----------------
__global__ void k_init() {
    int t = threadIdx.x;
    if (t < NTP) g_cnt[t] = 0;
    if (t == NTP) g_flag = 0;
}
__global__ void k_detect(const int* __restrict__ h) {
    int stride = gridDim.x * blockDim.x;
    int acc = 0;
    for (int j = blockIdx.x * blockDim.x + threadIdx.x; j < TA / 2; j += stride)
        acc |= h[2 * j + 1];
    unsigned any = __ballot_sync(0xffffffffu, acc != 0);
    if ((threadIdx.x & 31) == 0 && any) atomicOr(&g_flag, 1);
}
__device__ __forceinline__ int pick_at(const int* __restrict__ h, int i, int f) {
    return f ? h[i] : h[2 * i];
}
__global__ void k_build(const int* __restrict__ h) {
    __shared__ int sHist[NTP], sBase[NTP], sRank[NTP];
    int tid = threadIdx.x;
    if (tid < NTP) { sHist[tid] = 0; sRank[tid] = 0; }
    __syncthreads();
    int f = g_flag;
    int i = blockIdx.x * 512 + tid;
    int t = pick_at(h, i, f);
    atomicAdd(&sHist[t], 1);
    __syncthreads();
    if (tid < NTP) sBase[tid] = atomicAdd(&g_cnt[tid], sHist[tid]);
    __syncthreads();
    int p = atomicAdd(&sRank[t], 1);
    g_perm[t * TA + sBase[t] + p] = i;
}

// ---------------- smem layout (u32 indices) ----------------
#define U_ROWS 0
#define U_B1   128
#define U_B2   192
#define U_B3   256                       // 16 + pad
#define U_AH   288                       // 128*44 = 5632
#define U_AL   (U_AH + 5632)             // 5920
#define U_W1H  (U_AL + 5632)             // 11552 : 40*72 = 2880
#define U_W1L  (U_W1H + 2880)            // 14432
#define U_W2H  (U_W1L + 2880)            // 17312 : 32*72 = 2304
#define U_W2L  (U_W2H + 2304)            // 19616
#define U_W3H  (U_W2L + 2304)            // 21920 : 32*40 = 1280
#define U_W3L  (U_W3H + 1280)            // 23200
#define SMEM_U32 (U_W3L + 1280)          // 24480
#define SMEM_BYTES (SMEM_U32 * 4)        // 97920

// One 64-wide layer: warp w handles mtiles {2*(w&3), 2*(w&3)+1} x ntiles (w>>2)*4..+3.
__device__ __forceinline__ void layer_mma(
    const uint32_t* __restrict__ APh, const uint32_t* __restrict__ APl,
    const uint32_t* __restrict__ WPh, const uint32_t* __restrict__ WPl,
    int nks, int m0, int nb, int lane, float C[2][4][4]) {
    for (int ks = 0; ks < nks; ks++) {
        const int kp = ks * 8 + (lane & 3);
        uint32_t ah[2][4], al[2][4];
#pragma unroll
        for (int m = 0; m < 2; m++) {
            int r = m0 + m * 16 + (lane >> 2);
            const uint32_t* ph = APh + r * APS + kp;
            const uint32_t* pl = APl + r * APS + kp;
            ah[m][0] = ph[0];        al[m][0] = pl[0];
            ah[m][1] = ph[8 * APS];  al[m][1] = pl[8 * APS];
            ah[m][2] = ph[4];        al[m][2] = pl[4];
            ah[m][3] = ph[8 * APS + 4]; al[m][3] = pl[8 * APS + 4];
        }
#pragma unroll
        for (int nt = 0; nt < 4; nt++) {
            int n = (nb + nt) * 8 + (lane >> 2);
            uint32_t bh0 = WPh[kp * W12S + n];
            uint32_t bh1 = WPh[(kp + 4) * W12S + n];
            uint32_t bl0 = WPl[kp * W12S + n];
            uint32_t bl1 = WPl[(kp + 4) * W12S + n];
#pragma unroll
            for (int m = 0; m < 2; m++) {
                MMA_BF16(C[m][nt], ah[m], bh0, bh1);
                MMA_BF16(C[m][nt], al[m], bh0, bh1);
                MMA_BF16(C[m][nt], ah[m], bl0, bl1);
            }
        }
    }
}

// bias + relu + re-split -> AP (pairs over n, which is next layer's k)
__device__ __forceinline__ void epi_store(
    uint32_t* __restrict__ APh, uint32_t* __restrict__ APl,
    const float* __restrict__ Bv, int m0, int nb, int lane, float C[2][4][4]) {
#pragma unroll
    for (int m = 0; m < 2; m++) {
        int r0 = m0 + m * 16 + (lane >> 2);
#pragma unroll
        for (int nt = 0; nt < 4; nt++) {
            int n = (nb + nt) * 8 + (lane & 3) * 2;
            float b0 = Bv[n], b1 = Bv[n + 1];
            int kp = (nb + nt) * 4 + (lane & 3);
            uint32_t h, l;
            float v0 = fmaxf(C[m][nt][0] + b0, 0.0f);
            float v1 = fmaxf(C[m][nt][1] + b1, 0.0f);
            split2(v0, v1, h, l);
            APh[r0 * APS + kp] = h; APl[r0 * APS + kp] = l;
            v0 = fmaxf(C[m][nt][2] + b0, 0.0f);
            v1 = fmaxf(C[m][nt][3] + b1, 0.0f);
            split2(v0, v1, h, l);
            APh[(r0 + 8) * APS + kp] = h; APl[(r0 + 8) * APS + kp] = l;
        }
    }
}

__global__ void __launch_bounds__(NTHR, 2) mlp_hmma(
    const float* __restrict__ obs, const float* __restrict__ gp,
    const float* __restrict__ W1, const float* __restrict__ b1,
    const float* __restrict__ W2, const float* __restrict__ b2,
    const float* __restrict__ W3, const float* __restrict__ b3,
    const float* __restrict__ cW1, const float* __restrict__ cb1,
    const float* __restrict__ cW2, const float* __restrict__ cb2,
    const float* __restrict__ cW3, const float* __restrict__ cb3,
    float* __restrict__ out) {
    extern __shared__ uint32_t su[];
    int* sRows = (int*)(su + U_ROWS);
    float* sB1 = (float*)(su + U_B1);
    float* sB2 = (float*)(su + U_B2);
    float* sB3 = (float*)(su + U_B3);
    uint32_t* APh = su + U_AH;
    uint32_t* APl = su + U_AL;

    const int tid = threadIdx.x;
    const int lane = tid & 31;
    const int w = tid >> 5;
    const int cta = blockIdx.x;
    const bool critic = (cta >= NTP * ECTAS);

    int e = 0, j0, tstride, ntiles, cnt;
    if (!critic) {
        e = cta / ECTAS;
        j0 = cta - e * ECTAS;
        tstride = ECTAS;
        cnt = g_cnt[e];
        ntiles = (cnt + TILE - 1) / TILE;
    } else {
        j0 = cta - NTP * ECTAS;
        tstride = NCTA - NTP * ECTAS;   // 148
        cnt = TA;
        ntiles = TA / TILE;
    }

    // ---- stage weights once (pair-packed bf16 hi/lo) ----
    {
        const float* w1 = critic ? cW1 : (W1 + (size_t)e * 68 * HDIM);
        for (int i = tid; i < 40 * 64; i += NTHR) {
            int kp = i >> 6, n = i & 63;
            float f0 = (kp < 34) ? w1[(2 * kp) * 64 + n] : 0.0f;
            float f1 = (kp < 34) ? w1[(2 * kp + 1) * 64 + n] : 0.0f;
            uint32_t h, l;
            split2(f0, f1, h, l);
            su[U_W1H + kp * W12S + n] = h;
            su[U_W1L + kp * W12S + n] = l;
        }
        const float* w2 = critic ? cW2 : (W2 + (size_t)e * HDIM * HDIM);
        for (int i = tid; i < 32 * 64; i += NTHR) {
            int kp = i >> 6, n = i & 63;
            uint32_t h, l;
            split2(w2[(2 * kp) * 64 + n], w2[(2 * kp + 1) * 64 + n], h, l);
            su[U_W2H + kp * W12S + n] = h;
            su[U_W2L + kp * W12S + n] = l;
        }
        if (!critic) {
            const float* w3 = W3 + (size_t)e * HDIM * NA;
            for (int i = tid; i < 32 * 16; i += NTHR) {
                int kp = i >> 4, n = i & 15;
                uint32_t h, l;
                split2(w3[(2 * kp) * 16 + n], w3[(2 * kp + 1) * 16 + n], h, l);
                su[U_W3H + kp * W3S + n] = h;
                su[U_W3L + kp * W3S + n] = l;
            }
            if (tid < HDIM) { sB1[tid] = b1[e * HDIM + tid]; sB2[tid] = b2[e * HDIM + tid]; }
            if (tid < NA) sB3[tid] = b3[e * NA + tid];
        } else {
            for (int i = tid; i < 32 * 16; i += NTHR) {
                int kp = i >> 4, n = i & 15;
                uint32_t h = 0, l = 0;
                if (n == 0) split2(cW3[2 * kp], cW3[2 * kp + 1], h, l);
                su[U_W3H + kp * W3S + n] = h;
                su[U_W3L + kp * W3S + n] = l;
            }
            if (tid < HDIM) { sB1[tid] = cb1[tid]; sB2[tid] = cb2[tid]; }
            if (tid < NA) sB3[tid] = (tid == 0) ? cb3[0] : 0.0f;
        }
    }

    const int* permBase = g_perm + (critic ? 0 : e * TA);
    const int m0 = (w & 3) * 32;      // layers 1-2: mtiles 2(w&3), +1
    const int nb = (w >> 2) * 4;      // layers 1-2: ntiles nb..nb+3

    for (int t = j0; t < ntiles; t += tstride) {
        const int start = t * TILE;
        const int nvalid = min(TILE, cnt - start);

        __syncthreads();   // AP free (prev tile L3 reads done); covers weight staging

        // ---- stage X: 2 threads per row ----
        {
            int r = tid >> 1, half = tid & 1;
            int row;
            if (critic) row = start + r;
            else row = (r < nvalid) ? permBase[start + r] : permBase[start];
            if (half == 0) sRows[r] = row;
            const float4* src = (const float4*)(obs + (size_t)row * D_OBS) + 8 * half;
#pragma unroll
            for (int g = 0; g < 4; g++) {
                float4 va = src[2 * g], vb = src[2 * g + 1];
                uint32_t h0, l0, h1, l1, h2, l2, h3, l3;
                split2(va.x, va.y, h0, l0);
                split2(va.z, va.w, h1, l1);
                split2(vb.x, vb.y, h2, l2);
                split2(vb.z, vb.w, h3, l3);
                int kp = half * 16 + g * 4;
                *(uint4*)(APh + r * APS + kp) = make_uint4(h0, h1, h2, h3);
                *(uint4*)(APl + r * APS + kp) = make_uint4(l0, l1, l2, l3);
            }
            if (half) {   // gp features (cols 64-67) + zero pad to K=80
                float4 g4 = *(const float4*)(gp + (size_t)(row >> 7) * NTP);
                uint32_t h0, l0, h1, l1;
                split2(g4.x, g4.y, h0, l0);
                split2(g4.z, g4.w, h1, l1);
                *(uint4*)(APh + r * APS + 32) = make_uint4(h0, h1, 0u, 0u);
                *(uint4*)(APl + r * APS + 32) = make_uint4(l0, l1, 0u, 0u);
                *(uint4*)(APh + r * APS + 36) = make_uint4(0u, 0u, 0u, 0u);
                *(uint4*)(APl + r * APS + 36) = make_uint4(0u, 0u, 0u, 0u);
            }
        }
        __syncthreads();

        // ---- layer 1 (K=80 padded) ----
        float C[2][4][4];
#pragma unroll
        for (int m = 0; m < 2; m++)
#pragma unroll
            for (int nt = 0; nt < 4; nt++)
#pragma unroll
                for (int i = 0; i < 4; i++) C[m][nt][i] = 0.0f;
        layer_mma(APh, APl, su + U_W1H, su + U_W1L, 5, m0, nb, lane, C);
        __syncthreads();
        epi_store(APh, APl, sB1, m0, nb, lane, C);
        __syncthreads();

        // ---- layer 2 (K=64) ----
#pragma unroll
        for (int m = 0; m < 2; m++)
#pragma unroll
            for (int nt = 0; nt < 4; nt++)
#pragma unroll
                for (int i = 0; i < 4; i++) C[m][nt][i] = 0.0f;
        layer_mma(APh, APl, su + U_W2H, su + U_W2L, 4, m0, nb, lane, C);
        __syncthreads();
        epi_store(APh, APl, sB2, m0, nb, lane, C);
        __syncthreads();

        // ---- layer 3: logits / value. warp w -> mtile w (rows w*16..), ntiles 0,1 ----
        {
            float C3[2][4];
#pragma unroll
            for (int nt = 0; nt < 2; nt++)
#pragma unroll
                for (int i = 0; i < 4; i++) C3[nt][i] = 0.0f;
            const uint32_t* W3h = su + U_W3H;
            const uint32_t* W3l = su + U_W3L;
            for (int ks = 0; ks < 4; ks++) {
                const int kp = ks * 8 + (lane & 3);
                int r = w * 16 + (lane >> 2);
                const uint32_t* ph = APh + r * APS + kp;
                const uint32_t* pl = APl + r * APS + kp;
                uint32_t ah[4], al[4];
                ah[0] = ph[0]; ah[1] = ph[8 * APS]; ah[2] = ph[4]; ah[3] = ph[8 * APS + 4];
                al[0] = pl[0]; al[1] = pl[8 * APS]; al[2] = pl[4]; al[3] = pl[8 * APS + 4];
#pragma unroll
                for (int nt = 0; nt < 2; nt++) {
                    int n = nt * 8 + (lane >> 2);
                    uint32_t bh0 = W3h[kp * W3S + n];
                    uint32_t bh1 = W3h[(kp + 4) * W3S + n];
                    uint32_t bl0 = W3l[kp * W3S + n];
                    uint32_t bl1 = W3l[(kp + 4) * W3S + n];
                    MMA_BF16(C3[nt], ah, bh0, bh1);
                    MMA_BF16(C3[nt], al, bh0, bh1);
                    MMA_BF16(C3[nt], ah, bl0, bl1);
                }
            }
            int r0 = w * 16 + (lane >> 2);
            int r1 = r0 + 8;
            if (!critic) {
#pragma unroll
                for (int nt = 0; nt < 2; nt++) {
                    int n = nt * 8 + (lane & 3) * 2;
                    float b0 = sB3[n], b1 = sB3[n + 1];
                    if (r0 < nvalid) {
                        size_t o = (size_t)sRows[r0] * OUTC + n;
                        out[o] = C3[nt][0] + b0;
                        out[o + 1] = C3[nt][1] + b1;
                    }
                    if (r1 < nvalid) {
                        size_t o = (size_t)sRows[r1] * OUTC + n;
                        out[o] = C3[nt][2] + b0;
                        out[o + 1] = C3[nt][3] + b1;
                    }
                }
            } else {
                if ((lane & 3) == 0) {   // n == 0 column carries the value
                    float vb = sB3[0];
                    out[(size_t)sRows[r0] * OUTC + NA] = C3[0][0] + vb;
                    out[(size_t)sRows[r1] * OUTC + NA] = C3[0][2] + vb;
                }
            }
        }
    }
}

// ---------------- launch ----------------
extern "C" void kernel_launch(void* const* d_in, const int* in_sizes, int n_in,
                              void* d_out, int out_size) {
    const float* obs  = (const float*)d_in[0];
    const int*   hete = (const int*)d_in[1];
    const float* gp   = (const float*)d_in[2];
    const float* W1   = (const float*)d_in[3];
    const float* b1   = (const float*)d_in[4];
    const float* W2   = (const float*)d_in[5];
    const float* b2   = (const float*)d_in[6];
    const float* W3   = (const float*)d_in[7];
    const float* b3   = (const float*)d_in[8];
    const float* cW1  = (const float*)d_in[9];
    const float* cb1  = (const float*)d_in[10];
    const float* cW2  = (const float*)d_in[11];
    const float* cb2  = (const float*)d_in[12];
    const float* cW3  = (const float*)d_in[13];
    const float* cb3  = (const float*)d_in[14];
    float* out = (float*)d_out;

    cudaFuncSetAttribute(mlp_hmma, cudaFuncAttributeMaxDynamicSharedMemorySize,
                         SMEM_BYTES);

    k_init<<<1, 32>>>();
    k_detect<<<128, 256>>>(hete);
    k_build<<<TA / 512, 512>>>(hete);

    mlp_hmma<<<NCTA, NTHR, SMEM_BYTES>>>(obs, gp, W1, b1, W2, b2, W3, b3,
                                         cW1, cb1, cW2, cb2, cW3, cb3, out);
}